// round 2
// baseline (speedup 1.0000x reference)
#include <cuda_runtime.h>

// VanillaRNN persistent kernel for GB300 (sm_103a).
// h_{t+1} = tanh(W_hx * x_t + W_hh @ h_t + b_h), 1024 steps, then p = W_ph @ h + b_p.
//
// Design: 128 persistent CTAs = 16 row-groups x 8 batch-groups.
//  - Each CTA owns output tile h_new[32 rows x 32 batch cols].
//  - Its 32x512 slice of W_hh lives in SMEM for the whole kernel (no W traffic).
//  - h state double-buffered in __device__ global; reloaded per step via __ldcg (L2).
//  - Grid-wide step barrier: monotonic atomic counter (reset via cudaMemsetAsync).

#define HH    512
#define BB    256
#define TT    1024
#define NCLS  10

#define RGN   16            // row groups
#define BGN   8             // batch groups
#define HR    32            // rows per CTA
#define BT    32            // batch cols per CTA
#define NCTA  (RGN * BGN)   // 128
#define NTHR  256

#define W_PAD 516           // 512 + 4 (bank-conflict-free W row stride, 16B aligned)
#define H_PAD 36            // 32 + 4  (hs row stride, 16B aligned)

#define SMEM_FLOATS (HR * W_PAD + HH * H_PAD + BT)
#define SMEM_BYTES  (SMEM_FLOATS * 4)

__device__ float    g_h[2][HH][BB];   // double-buffered hidden state
__device__ unsigned g_bar;            // grid barrier counter (memset to 0 per launch)

__global__ void __launch_bounds__(NTHR, 1) rnn_persistent(
    const float* __restrict__ x,       // [BB][TT]
    const float* __restrict__ h_init,  // [HH]
    const float* __restrict__ W_hx,    // [HH]
    const float* __restrict__ W_hh,    // [HH][HH]
    const float* __restrict__ b_h,     // [HH]
    const float* __restrict__ W_ph,    // [NCLS][HH]
    const float* __restrict__ b_p,     // [NCLS]
    float* __restrict__ out)           // [BB][NCLS]
{
    extern __shared__ float smem[];
    float* Wr = smem;                  // [HR][W_PAD]   resident W_hh slice
    float* hs = smem + HR * W_PAD;     // [HH][H_PAD]   current h (this CTA's 32 cols)
    float* xs = hs + HH * H_PAD;       // [BT]          x_t for this CTA's cols

    const int tid   = threadIdx.x;
    const int cta   = blockIdx.x;
    const int rg    = cta >> 3;        // 0..15
    const int bg    = cta & 7;         // 0..7
    const int rbase = rg * HR;
    const int cbase = bg * BT;

    // ---- load resident W_hh slice (32 rows x 512) ----
    for (int i = tid; i < HR * (HH / 4); i += NTHR) {
        int r  = i >> 7;               // i / 128
        int kq = i & 127;
        float4 v = *reinterpret_cast<const float4*>(W_hh + (rbase + r) * HH + (kq << 2));
        *reinterpret_cast<float4*>(Wr + r * W_PAD + (kq << 2)) = v;
    }

    // ---- init hs with h_init broadcast (step 0 input) ----
    for (int k = tid; k < HH; k += NTHR) {
        float v = h_init[k];
        float* row = hs + k * H_PAD;
        #pragma unroll
        for (int c = 0; c < BT; ++c) row[c] = v;
    }

    // ---- per-thread 2x2 microtile mapping (broadcast-friendly) ----
    const int warp = tid >> 5, lane = tid & 31;
    const int wr = warp >> 1, wc = warp & 1;   // 4 x 2 warp grid
    const int rp = lane >> 3, cp = lane & 7;   // 4 row-pairs x 8 col-pairs per warp
    const int r0 = ((wr << 2) + rp) << 1;      // local row  (even), +1 is pair
    const int c0 = ((wc << 3) + cp) << 1;      // local col  (even), +1 is pair

    const float bh0 = b_h[rbase + r0];
    const float bh1 = b_h[rbase + r0 + 1];
    const float wx0 = W_hx[rbase + r0];
    const float wx1 = W_hx[rbase + r0 + 1];

    const float* w0p = Wr + r0 * W_PAD;
    const float* w1p = w0p + W_PAD;
    const float* hcp = hs + c0;

    __syncthreads();

    for (int s = 0; s < TT; ++s) {
        // ---- refresh h tile from global (written by all CTAs last step) ----
        if (s > 0) {
            const int buf = s & 1;
            #pragma unroll
            for (int i = tid; i < HH * (BT / 4); i += NTHR) {
                int k  = i >> 3;
                int cq = i & 7;
                float4 v = __ldcg(reinterpret_cast<const float4*>(
                               &g_h[buf][k][cbase + (cq << 2)]));
                *reinterpret_cast<float4*>(hs + k * H_PAD + (cq << 2)) = v;
            }
        }
        if (tid < BT) xs[tid] = x[(cbase + tid) * TT + s];
        __syncthreads();

        const float xc0 = xs[c0], xc1 = xs[c0 + 1];
        float a00 = fmaf(wx0, xc0, bh0);
        float a01 = fmaf(wx0, xc1, bh0);
        float a10 = fmaf(wx1, xc0, bh1);
        float a11 = fmaf(wx1, xc1, bh1);

        // ---- 512-deep dot products, 4 outputs per thread ----
        #pragma unroll 8
        for (int k = 0; k < HH; k += 4) {
            const float4 wa = *reinterpret_cast<const float4*>(w0p + k);
            const float4 wb = *reinterpret_cast<const float4*>(w1p + k);
            const float2 h0 = *reinterpret_cast<const float2*>(hcp + (k + 0) * H_PAD);
            const float2 h1 = *reinterpret_cast<const float2*>(hcp + (k + 1) * H_PAD);
            const float2 h2 = *reinterpret_cast<const float2*>(hcp + (k + 2) * H_PAD);
            const float2 h3 = *reinterpret_cast<const float2*>(hcp + (k + 3) * H_PAD);
            a00 = fmaf(wa.x, h0.x, a00); a01 = fmaf(wa.x, h0.y, a01);
            a10 = fmaf(wb.x, h0.x, a10); a11 = fmaf(wb.x, h0.y, a11);
            a00 = fmaf(wa.y, h1.x, a00); a01 = fmaf(wa.y, h1.y, a01);
            a10 = fmaf(wb.y, h1.x, a10); a11 = fmaf(wb.y, h1.y, a11);
            a00 = fmaf(wa.z, h2.x, a00); a01 = fmaf(wa.z, h2.y, a01);
            a10 = fmaf(wb.z, h2.x, a10); a11 = fmaf(wb.z, h2.y, a11);
            a00 = fmaf(wa.w, h3.x, a00); a01 = fmaf(wa.w, h3.y, a01);
            a10 = fmaf(wb.w, h3.x, a10); a11 = fmaf(wb.w, h3.y, a11);
        }

        a00 = tanhf(a00); a01 = tanhf(a01);
        a10 = tanhf(a10); a11 = tanhf(a11);

        const int wbuf = (s + 1) & 1;
        *reinterpret_cast<float2*>(&g_h[wbuf][rbase + r0    ][cbase + c0]) = make_float2(a00, a01);
        *reinterpret_cast<float2*>(&g_h[wbuf][rbase + r0 + 1][cbase + c0]) = make_float2(a10, a11);

        // ---- grid-wide step barrier (monotonic counter, no reset races) ----
        __threadfence();          // publish this thread's h stores (gpu scope)
        __syncthreads();
        if (tid == 0) {
            atomicAdd(&g_bar, 1u);
            const unsigned target = (unsigned)NCTA * (unsigned)(s + 1);
            while (*((volatile unsigned*)&g_bar) < target) { }
            __threadfence();      // acquire
        }
        __syncthreads();
    }

    // ---- final projection: out[b][n] = b_p[n] + sum_k W_ph[n][k] * h_last[k][b] ----
    // h_last lives in g_h[0] (step 1023 wrote buffer (1023+1)&1 == 0).
    if (rg == 0) {
        // reuse Wr region for W_ph (10*512 floats, contiguous)
        for (int i = tid; i < (NCLS * HH) / 4; i += NTHR) {
            float4 v = *reinterpret_cast<const float4*>(W_ph + (i << 2));
            *reinterpret_cast<float4*>(Wr + (i << 2)) = v;
        }
        for (int i = tid; i < HH * (BT / 4); i += NTHR) {
            int k = i >> 3, cq = i & 7;
            float4 v = __ldcg(reinterpret_cast<const float4*>(
                           &g_h[0][k][cbase + (cq << 2)]));
            *reinterpret_cast<float4*>(hs + k * H_PAD + (cq << 2)) = v;
        }
        __syncthreads();
        for (int idx = tid; idx < BT * NCLS; idx += NTHR) {
            int cl = idx / NCLS;
            int n  = idx - cl * NCLS;
            float acc = b_p[n];
            const float* wrow = Wr + n * HH;
            const float* hcol = hs + cl;
            #pragma unroll 8
            for (int k = 0; k < HH; ++k)
                acc = fmaf(wrow[k], hcol[k * H_PAD], acc);
            out[(cbase + cl) * NCLS + n] = acc;
        }
    }
}

extern "C" void kernel_launch(void* const* d_in, const int* in_sizes, int n_in,
                              void* d_out, int out_size) {
    const float* x      = (const float*)d_in[0];
    const float* h_init = (const float*)d_in[1];
    const float* W_hx   = (const float*)d_in[2];
    const float* W_hh   = (const float*)d_in[3];
    const float* b_h    = (const float*)d_in[4];
    const float* W_ph   = (const float*)d_in[5];
    const float* b_p    = (const float*)d_in[6];
    float* out = (float*)d_out;

    // reset the grid barrier counter (graph-capturable memset node)
    void* barp = nullptr;
    cudaGetSymbolAddress(&barp, g_bar);
    cudaMemsetAsync(barp, 0, sizeof(unsigned), 0);

    cudaFuncSetAttribute(rnn_persistent,
                         cudaFuncAttributeMaxDynamicSharedMemorySize, SMEM_BYTES);

    rnn_persistent<<<NCTA, NTHR, SMEM_BYTES, 0>>>(x, h_init, W_hx, W_hh, b_h,
                                                  W_ph, b_p, out);
}